// round 11
// baseline (speedup 1.0000x reference)
#include <cuda_runtime.h>
#include <cuda_bf16.h>
#include <cstdint>
#include <cstddef>
#include <math.h>

// Dims
#define Bn 32
#define Sn 128
#define Pn 32
#define In 512
#define Hn 512
#define G3 1536
#define On 10

// Output layout: out[32,10] | states[32,128,512] | context[32,512] | alpha[32,128]
#define OFF_OUT 0
#define OFF_ST  320
#define OFF_CTX 2097472
#define OFF_AL  2113856

// -------- scratch (__device__ globals; no allocations allowed) --------------
__device__ float g_conv[Sn*Bn*In];
__device__ float g_emb [Sn*Bn*In];
__device__ float g_gi0 [Sn*Bn*G3];
__device__ float g_st0 [Sn*Bn*Hn];
__device__ float g_gi1 [Sn*Bn*G3];
__device__ float g_hT2[2*Hn*Bn];     // double-buffered h, transposed [j][b]
// per-COLUMN step flags (512 columns), each on its own 128B line. Two arrays
// (one per layer); each layer resets the OTHER layer's array (stream-ordered).
__device__ __align__(128) unsigned g_flagA[512*32];
__device__ __align__(128) unsigned g_flagB[512*32];

// -------- helpers -----------------------------------------------------------
__device__ __forceinline__ float wred(float v) {
    #pragma unroll
    for (int o = 16; o; o >>= 1) v += __shfl_xor_sync(0xffffffffu, v, o);
    return v;
}
__device__ __forceinline__ unsigned ld_acq(const unsigned* p) {
    unsigned v;
    asm volatile("ld.acquire.gpu.u32 %0,[%1];" : "=r"(v) : "l"(p) : "memory");
    return v;
}
__device__ __forceinline__ void st_rel(unsigned* p, unsigned v) {
    asm volatile("st.release.gpu.u32 [%0],%1;" :: "l"(p), "r"(v) : "memory");
}
__device__ __forceinline__ float ldcg(const float* p) {
    float v;
    asm volatile("ld.global.cg.f32 %0,[%1];" : "=f"(v) : "l"(p));
    return v;
}
#define FMA2(d,a,b) asm("fma.rn.f32x2 %0,%1,%2,%0;" : "+l"(d) : "l"(a), "l"(b))
#define BCAST2(d,f) asm("mov.b64 %0,{%1,%1};" : "=l"(d) : "f"(f))
#define PACK2(d,x,y) asm("mov.b64 %0,{%1,%2};" : "=l"(d) : "f"(x), "f"(y))
#define UNPK2(x,y,d) asm("mov.b64 {%0,%1},%2;" : "=f"(x), "=f"(y) : "l"(d))

// ======== K1: conv-attention pooling over P (conv_b cancels in softmax) =====
__global__ __launch_bounds__(256)
void conv_pool_kernel(const float* __restrict__ in, const float* __restrict__ conv_w,
                      float* __restrict__ conv_all) {
    __shared__ float cw[In];
    __shared__ float sc[Pn];
    __shared__ float at[Pn];
    const int tid = threadIdx.x;
    const int bx = blockIdx.x;          // b*S + s
    const int b = bx >> 7, s = bx & 127;
    const float* base = in + (size_t)bx * (Pn * In);

    if (tid < 128) ((float4*)cw)[tid] = ((const float4*)conv_w)[tid];
    __syncthreads();

    const int w = tid >> 5, lane = tid & 31;
    #pragma unroll
    for (int q = 0; q < 4; q++) {
        int p = w * 4 + q;
        const float4* row = (const float4*)(base + (size_t)p * In);
        const float4* cw4 = (const float4*)cw;
        float acc = 0.f;
        for (int kk = lane; kk < 128; kk += 32) {
            float4 x = row[kk], y = cw4[kk];
            acc += x.x*y.x + x.y*y.y + x.z*y.z + x.w*y.w;
        }
        acc = wred(acc);
        if (lane == 0) sc[p] = acc;
    }
    __syncthreads();

    if (tid < 32) {
        float v = sc[tid], m = v;
        #pragma unroll
        for (int o = 16; o; o >>= 1) m = fmaxf(m, __shfl_xor_sync(0xffffffffu, m, o));
        float e = expf(v - m);
        float ssum = wred(e);
        at[tid] = e / ssum;
    }
    __syncthreads();

    float* dst = conv_all + ((size_t)s * Bn + b) * In;   // row = s*32+b
    for (int i = tid; i < In; i += 256) {
        float acc = 0.f;
        #pragma unroll 8
        for (int p = 0; p < Pn; p++) acc += at[p] * base[(size_t)p * In + i];
        dst[i] = acc;
    }
}

// ======== GEMM  C[M,N] = act(A[M,512] @ W[N,512]^T + bias) ==================
// 128x128 tile, 256 threads, 8x8 thread tile (32 FMA2 per k per thread).
#define GBM 128
#define GBN 128
#define GBK 16
__global__ __launch_bounds__(256)
void gemm_tn(const float* __restrict__ A, const float* __restrict__ W,
             const float* __restrict__ bias, float* __restrict__ C,
             int N, int act) {
    __shared__ float As[GBK][GBM + 4];
    __shared__ float Ws[GBK][GBN + 4];
    const int tid = threadIdx.x;
    const int row0 = blockIdx.y * GBM;
    const int col0 = blockIdx.x * GBN;
    const int m0 = (tid >> 4) * 8;      // 0..120
    const int n0 = (tid & 15) * 8;      // 0..120
    unsigned long long acc[8][4];
    #pragma unroll
    for (int i = 0; i < 8; i++)
        #pragma unroll
        for (int j = 0; j < 4; j++) acc[i][j] = 0ULL;

    for (int k0 = 0; k0 < 512; k0 += GBK) {
        #pragma unroll
        for (int l = 0; l < 2; l++) {
            int idx = tid + l * 256;          // 0..511
            int m = idx & 127, kb = idx >> 7; // kb 0..3, 4 k each
            float4 v = *(const float4*)(A + (size_t)(row0 + m) * 512 + k0 + kb * 4);
            As[kb*4+0][m] = v.x; As[kb*4+1][m] = v.y;
            As[kb*4+2][m] = v.z; As[kb*4+3][m] = v.w;
        }
        #pragma unroll
        for (int l = 0; l < 2; l++) {
            int idx = tid + l * 256;
            int n = idx & 127, kb = idx >> 7;
            float4 v = *(const float4*)(W + (size_t)(col0 + n) * 512 + k0 + kb * 4);
            Ws[kb*4+0][n] = v.x; Ws[kb*4+1][n] = v.y;
            Ws[kb*4+2][n] = v.z; Ws[kb*4+3][n] = v.w;
        }
        __syncthreads();
        #pragma unroll
        for (int k = 0; k < GBK; k++) {
            float4 a0 = *(const float4*)&As[k][m0];
            float4 a1 = *(const float4*)&As[k][m0 + 4];
            float4 w0 = *(const float4*)&Ws[k][n0];
            float4 w1 = *(const float4*)&Ws[k][n0 + 4];
            unsigned long long wp0, wp1, wp2, wp3;
            PACK2(wp0, w0.x, w0.y);
            PACK2(wp1, w0.z, w0.w);
            PACK2(wp2, w1.x, w1.y);
            PACK2(wp3, w1.z, w1.w);
            float am[8] = {a0.x,a0.y,a0.z,a0.w,a1.x,a1.y,a1.z,a1.w};
            #pragma unroll
            for (int i = 0; i < 8; i++) {
                unsigned long long ai;
                BCAST2(ai, am[i]);
                FMA2(acc[i][0], ai, wp0);
                FMA2(acc[i][1], ai, wp1);
                FMA2(acc[i][2], ai, wp2);
                FMA2(acc[i][3], ai, wp3);
            }
        }
        __syncthreads();
    }
    float bv[8];
    #pragma unroll
    for (int j = 0; j < 8; j++) bv[j] = bias ? bias[col0 + n0 + j] : 0.f;
    #pragma unroll
    for (int i = 0; i < 8; i++) {
        float c[8];
        UNPK2(c[0], c[1], acc[i][0]);
        UNPK2(c[2], c[3], acc[i][1]);
        UNPK2(c[4], c[5], acc[i][2]);
        UNPK2(c[6], c[7], acc[i][3]);
        #pragma unroll
        for (int j = 0; j < 8; j++) {
            c[j] += bv[j];
            if (act == 1) c[j] = fminf(1.f, fmaxf(-1.f, c[j]));
        }
        float4 o0 = {c[0], c[1], c[2], c[3]};
        float4 o1 = {c[4], c[5], c[6], c[7]};
        *(float4*)(C + (size_t)(row0 + m0 + i) * N + col0 + n0) = o0;
        *(float4*)(C + (size_t)(row0 + m0 + i) * N + col0 + n0 + 4) = o1;
    }
}

// ======== GRU persistent recurrence (per-column flags, split-role barrier) ==
// grid=128 CTAs, 512 thr (16 warps). CTA c owns h-columns [4c,4c+4).
// Dot: warp w handles slice k0 = q*128+(w&3)*32, q=((w>>2)+cta)&3; polls its
// 32 COLUMN flags (one lane per flag line) then ldcg h from L2, MLP=32.
// Barrier: warps 4-15 bar.arrive (non-blocking, run ahead one step max);
// warps 0-3 bar.sync then do gate math for column jg=cta*4+w across 32 b.
// Two barrier IDs alternate by step parity (phase separation). red is
// double-buffered by parity. Gate warp publishes its own column flag with
// st.release after __syncwarp (single-writer, one 128B h line per column).
#define SM_WP   0
#define SM_RED  32768
#define RED_HALF 6656
#define SM_BH   (32768 + 2*RED_HALF*4)
#define GRU_SMEM (32768 + 2*RED_HALF*4 + 64)

__global__ __launch_bounds__(512)
void gru_kernel(const float* __restrict__ gi, const float* __restrict__ Whh,
                const float* __restrict__ bhh, float* __restrict__ st_out,
                int lay1) {
    extern __shared__ char sm[];
    float* wp  = (float*)(sm + SM_WP);    // [k][16] floats; cols c=0..11 (c=g*4+jl)
    float* red = (float*)(sm + SM_RED);   // 2 x [(w*32+b)*13 + c]
    float* bh  = (float*)(sm + SM_BH);    // [12]
    const int tid = threadIdx.x;
    const int cta = blockIdx.x;

    unsigned* flg = lay1 ? g_flagB : g_flagA;
    // reset the OTHER layer's flags for this CTA's 4 columns
    if (tid < 4) (lay1 ? g_flagA : g_flagB)[(cta * 4 + tid) * 32] = 0;

    // weights: wp[k*16 + c] = Whh[(g*512 + cta*4 + jl)*512 + k], c = g*4+jl
    for (int i = tid; i < 6144; i += 512) {
        int c = i >> 9, k = i & 511;
        int g = c >> 2, jl = c & 3;
        wp[k * 16 + c] = Whh[(size_t)(g * 512 + cta * 4 + jl) * 512 + k];
    }
    if (tid < 12) bh[tid] = bhh[(tid >> 2) * 512 + cta * 4 + (tid & 3)];
    __syncthreads();

    const int lane = tid & 31, w = tid >> 5;
    const int q = ((w >> 2) + cta) & 3;          // chunk this warp consumes
    const int k0 = q * 128 + (w & 3) * 32;       // warp's 32-k slice
    const unsigned* myflag = &flg[(k0 + lane) * 32];   // one column flag per lane
    // gate identity (warps 0-3): column jg, lane = batch
    const int jl = w;                            // valid when w < 4
    const int jg = cta * 4 + jl;

    float giv0 = 0.f, giv1 = 0.f, giv2 = 0.f, ho = 0.f;
    if (w < 4) {
        giv0 = __ldg(gi + (size_t)lane * G3 + jg);
        giv1 = __ldg(gi + (size_t)lane * G3 + 512 + jg);
        giv2 = __ldg(gi + (size_t)lane * G3 + 1024 + jg);
    }

    for (int s = 0; s < 128; s++) {
        float* rbuf = red + (s & 1) * RED_HALF;
        if (s > 0) {
            // ---- warp-autonomous wait: 32 column flags, one per lane ----
            {
                unsigned tgt = (unsigned)s;
                while (!__all_sync(0xffffffffu, ld_acq(myflag) >= tgt)) { }
            }
            // ---- direct L2 read (cg): all 32 h loads in flight at once ----
            const float* hb = g_hT2 + ((s + 1) & 1) * (Hn * Bn) + (size_t)k0 * 32 + lane;
            float hr[32];
            #pragma unroll
            for (int i = 0; i < 32; i++) hr[i] = ldcg(hb + i * 32);

            unsigned long long acc[6];
            #pragma unroll
            for (int p = 0; p < 6; p++) acc[p] = 0ULL;
            #pragma unroll
            for (int i = 0; i < 32; i++) {
                unsigned long long h2;
                BCAST2(h2, hr[i]);
                const ulonglong2* wk = (const ulonglong2*)(wp + (k0 + i) * 16);
                ulonglong2 A = wk[0], Bv = wk[1], Cv = wk[2];
                FMA2(acc[0], h2, A.x);  FMA2(acc[1], h2, A.y);
                FMA2(acc[2], h2, Bv.x); FMA2(acc[3], h2, Bv.y);
                FMA2(acc[4], h2, Cv.x); FMA2(acc[5], h2, Cv.y);
            }
            float* rr = rbuf + (w * 32 + lane) * 13;
            #pragma unroll
            for (int p = 0; p < 6; p++) {
                float x, y;
                UNPK2(x, y, acc[p]);
                rr[2 * p] = x; rr[2 * p + 1] = y;
            }
        }

        const int bid = 1 + (s & 1);             // alternate barrier ids
        if (w >= 4) {
            // producers-of-reduction only: non-blocking arrive, run ahead
            asm volatile("bar.arrive %0, 512;" :: "r"(bid) : "memory");
        } else {
            asm volatile("bar.sync %0, 512;" :: "r"(bid) : "memory");
            // ---- gate math: column jg, 32 batches across lanes ----
            float gh0 = 0.f, gh1 = 0.f, gh2 = 0.f;
            if (s > 0) {
                #pragma unroll
                for (int ww = 0; ww < 16; ww++) {
                    const float* rr = rbuf + (ww * 32 + lane) * 13;
                    gh0 += rr[jl];
                    gh1 += rr[4 + jl];
                    gh2 += rr[8 + jl];
                }
            }
            float r = 1.f / (1.f + expf(-(giv0 + gh0 + bh[jl])));
            float z = 1.f / (1.f + expf(-(giv1 + gh1 + bh[4 + jl])));
            float nn = tanhf(giv2 + r * (gh2 + bh[8 + jl]));
            float hn = (1.f - z) * nn + z * ho;
            ho = hn;
            // one 128B line per gate warp
            g_hT2[(s & 1) * (Hn * Bn) + jg * 32 + lane] = hn;
            __syncwarp();
            if (lane == 0) st_rel(&flg[jg * 32], (unsigned)(s + 1));
            // off-critical-path: states write + next gi prefetch
            size_t oidx = lay1 ? ((size_t)lane * 128 + s) * 512 + jg
                               : ((size_t)s * 32 + lane) * 512 + jg;
            st_out[oidx] = hn;
            if (s < 127) {
                size_t gib = ((size_t)(s + 1) * 32 + lane) * (size_t)G3;
                giv0 = __ldg(gi + gib + jg);
                giv1 = __ldg(gi + gib + 512 + jg);
                giv2 = __ldg(gi + gib + 1024 + jg);
            }
        }
    }
}

// ======== final: time-attention + linear + softmax ==========================
// states layout here: [b][s][h] (written directly by layer-1 GRU into d_out)
__global__ __launch_bounds__(256)
void final_kernel(const float* __restrict__ states, const float* __restrict__ attw,
                  const float* __restrict__ demoip, const float* __restrict__ linW,
                  const float* __restrict__ linb, float* __restrict__ out) {
    __shared__ float aw[512];
    __shared__ float lg[128];
    __shared__ float al[128];
    __shared__ float ctx[512];
    __shared__ float o10[10];
    const int tid = threadIdx.x, b = blockIdx.x;
    const int w = tid >> 5, lane = tid & 31;
    const float* stb = states + (size_t)b * 128 * 512;

    for (int h = tid; h < 512; h += 256) aw[h] = attw[h];
    __syncthreads();

    for (int s = w; s < 128; s += 8) {
        const float* row = stb + (size_t)s * 512;
        float acc = 0.f;
        for (int h = lane; h < 512; h += 32) acc += row[h] * aw[h];
        acc = wred(acc);
        if (lane == 0) lg[s] = acc;
    }
    __syncthreads();

    if (tid < 32) {
        float v[4]; float m = -1e30f;
        #pragma unroll
        for (int q = 0; q < 4; q++) { v[q] = lg[tid + q * 32]; m = fmaxf(m, v[q]); }
        #pragma unroll
        for (int o = 16; o; o >>= 1) m = fmaxf(m, __shfl_xor_sync(0xffffffffu, m, o));
        float ssum = 0.f;
        #pragma unroll
        for (int q = 0; q < 4; q++) { v[q] = expf(v[q] - m); ssum += v[q]; }
        ssum = wred(ssum);
        #pragma unroll
        for (int q = 0; q < 4; q++) {
            float a = v[q] / ssum;
            al[tid + q * 32] = a;
            out[OFF_AL + b * 128 + tid + q * 32] = a;
        }
    }
    __syncthreads();

    for (int h = tid; h < 512; h += 256) {
        float acc = 0.f;
        for (int s = 0; s < 128; s++) acc += al[s] * stb[(size_t)s * 512 + h];
        ctx[h] = acc;
        out[OFF_CTX + b * 512 + h] = acc;
    }
    __syncthreads();

    if (tid < 10) {
        float acc = linb[tid];
        const float* wrow = linW + tid * 515;
        for (int h = 0; h < 512; h++) acc += ctx[h] * wrow[h];
        for (int d = 0; d < 3; d++) acc += demoip[b * 3 + d] * wrow[512 + d];
        o10[tid] = acc;
    }
    __syncthreads();
    if (tid < 10) {
        float m = -1e30f;
        for (int o = 0; o < 10; o++) m = fmaxf(m, o10[o]);
        float e = expf(o10[tid] - m), ssum = 0.f;
        for (int o = 0; o < 10; o++) ssum += expf(o10[o] - m);
        out[OFF_OUT + b * 10 + tid] = e / ssum;
    }
}

// ======== launch ============================================================
extern "C" void kernel_launch(void* const* d_in, const int* in_sizes, int n_in,
                              void* d_out, int out_size) {
    // batch_size may or may not be materialized as input[2] (size-1 scalar).
    int sh = (in_sizes[2] == 1) ? 1 : 0;

    const float* inp   = (const float*)d_in[0];
    const float* demo  = (const float*)d_in[1];
    const float* convw = (const float*)d_in[2 + sh];
    // conv_b at [3+sh] cancels in the softmax; unused.
    const float* embW  = (const float*)d_in[4 + sh];
    const float* Wi0   = (const float*)d_in[5 + sh];
    const float* Wh0   = (const float*)d_in[6 + sh];
    const float* bi0   = (const float*)d_in[7 + sh];
    const float* bh0   = (const float*)d_in[8 + sh];
    const float* Wi1   = (const float*)d_in[9 + sh];
    const float* Wh1   = (const float*)d_in[10 + sh];
    const float* bi1   = (const float*)d_in[11 + sh];
    const float* bh1   = (const float*)d_in[12 + sh];
    const float* attw  = (const float*)d_in[13 + sh];
    const float* linW  = (const float*)d_in[14 + sh];
    const float* linb  = (const float*)d_in[15 + sh];
    float* out = (float*)d_out;

    cudaFuncSetAttribute(gru_kernel, cudaFuncAttributeMaxDynamicSharedMemorySize, GRU_SMEM);

    void *pc, *pe, *p0, *ps0, *p1;
    cudaGetSymbolAddress(&pc, g_conv);
    cudaGetSymbolAddress(&pe, g_emb);
    cudaGetSymbolAddress(&p0, g_gi0);
    cudaGetSymbolAddress(&ps0, g_st0);
    cudaGetSymbolAddress(&p1, g_gi1);

    conv_pool_kernel<<<Bn * Sn, 256>>>(inp, convw, (float*)pc);

    dim3 ge(In / GBN, (Sn * Bn) / GBM);   // (4, 32)
    dim3 gg(G3 / GBN, (Sn * Bn) / GBM);   // (12, 32)
    gemm_tn<<<ge, 256>>>((const float*)pc, embW, nullptr, (float*)pe, In, 1);
    gemm_tn<<<gg, 256>>>((const float*)pe, Wi0, bi0, (float*)p0, G3, 0);

    gru_kernel<<<128, 512, GRU_SMEM>>>((const float*)p0, Wh0, bh0, (float*)ps0, 0);

    gemm_tn<<<gg, 256>>>((const float*)ps0, Wi1, bi1, (float*)p1, G3, 0);

    gru_kernel<<<128, 512, GRU_SMEM>>>((const float*)p1, Wh1, bh1, out + OFF_ST, 1);

    final_kernel<<<Bn, 256>>>(out + OFF_ST, attw, demo, linW, linb, out);
}

// round 12
// speedup vs baseline: 1.3605x; 1.3605x over previous
#include <cuda_runtime.h>
#include <cuda_bf16.h>
#include <cstdint>
#include <cstddef>
#include <math.h>

// Dims
#define Bn 32
#define Sn 128
#define Pn 32
#define In 512
#define Hn 512
#define G3 1536
#define On 10

// Output layout: out[32,10] | states[32,128,512] | context[32,512] | alpha[32,128]
#define OFF_OUT 0
#define OFF_ST  320
#define OFF_CTX 2097472
#define OFF_AL  2113856

// -------- scratch (__device__ globals; no allocations allowed) --------------
__device__ float g_conv[Sn*Bn*In];
__device__ float g_emb [Sn*Bn*In];
__device__ float g_gi0 [Sn*Bn*G3];
__device__ float g_st0 [Sn*Bn*Hn];
__device__ float g_gi1 [Sn*Bn*G3];
__device__ float g_hT2[2*Hn*Bn];     // double-buffered h, transposed [j][b]
// per-CTA step flags, each on its own 128B line. Two arrays (one per layer);
// each layer resets the OTHER layer's array (stream-ordered, race-free).
__device__ __align__(128) unsigned g_flagA[128*32];
__device__ __align__(128) unsigned g_flagB[128*32];

// -------- helpers -----------------------------------------------------------
__device__ __forceinline__ float wred(float v) {
    #pragma unroll
    for (int o = 16; o; o >>= 1) v += __shfl_xor_sync(0xffffffffu, v, o);
    return v;
}
__device__ __forceinline__ unsigned ld_acq(const unsigned* p) {
    unsigned v;
    asm volatile("ld.acquire.gpu.u32 %0,[%1];" : "=r"(v) : "l"(p) : "memory");
    return v;
}
__device__ __forceinline__ void st_rel(unsigned* p, unsigned v) {
    asm volatile("st.release.gpu.u32 [%0],%1;" :: "l"(p), "r"(v) : "memory");
}
__device__ __forceinline__ float ldcg(const float* p) {
    float v;
    asm volatile("ld.global.cg.f32 %0,[%1];" : "=f"(v) : "l"(p));
    return v;
}
#define FMA2(d,a,b) asm("fma.rn.f32x2 %0,%1,%2,%0;" : "+l"(d) : "l"(a), "l"(b))
#define BCAST2(d,f) asm("mov.b64 %0,{%1,%1};" : "=l"(d) : "f"(f))
#define PACK2(d,x,y) asm("mov.b64 %0,{%1,%2};" : "=l"(d) : "f"(x), "f"(y))
#define UNPK2(x,y,d) asm("mov.b64 {%0,%1},%2;" : "=f"(x), "=f"(y) : "l"(d))

// ======== K1: conv-attention pooling over P (conv_b cancels in softmax) =====
__global__ __launch_bounds__(256)
void conv_pool_kernel(const float* __restrict__ in, const float* __restrict__ conv_w,
                      float* __restrict__ conv_all) {
    __shared__ float cw[In];
    __shared__ float sc[Pn];
    __shared__ float at[Pn];
    const int tid = threadIdx.x;
    const int bx = blockIdx.x;          // b*S + s
    const int b = bx >> 7, s = bx & 127;
    const float* base = in + (size_t)bx * (Pn * In);

    if (tid < 128) ((float4*)cw)[tid] = ((const float4*)conv_w)[tid];
    __syncthreads();

    const int w = tid >> 5, lane = tid & 31;
    #pragma unroll
    for (int q = 0; q < 4; q++) {
        int p = w * 4 + q;
        const float4* row = (const float4*)(base + (size_t)p * In);
        const float4* cw4 = (const float4*)cw;
        float acc = 0.f;
        for (int kk = lane; kk < 128; kk += 32) {
            float4 x = row[kk], y = cw4[kk];
            acc += x.x*y.x + x.y*y.y + x.z*y.z + x.w*y.w;
        }
        acc = wred(acc);
        if (lane == 0) sc[p] = acc;
    }
    __syncthreads();

    if (tid < 32) {
        float v = sc[tid], m = v;
        #pragma unroll
        for (int o = 16; o; o >>= 1) m = fmaxf(m, __shfl_xor_sync(0xffffffffu, m, o));
        float e = expf(v - m);
        float ssum = wred(e);
        at[tid] = e / ssum;
    }
    __syncthreads();

    float* dst = conv_all + ((size_t)s * Bn + b) * In;   // row = s*32+b
    for (int i = tid; i < In; i += 256) {
        float acc = 0.f;
        #pragma unroll 8
        for (int p = 0; p < Pn; p++) acc += at[p] * base[(size_t)p * In + i];
        dst[i] = acc;
    }
}

// ======== GEMM  C[M,N] = act(A[M,512] @ W[N,512]^T + bias) ==================
#define GBM 128
#define GBN 64
#define GBK 32
__global__ __launch_bounds__(256)
void gemm_tn(const float* __restrict__ A, const float* __restrict__ W,
             const float* __restrict__ bias, float* __restrict__ C,
             int N, int act) {
    __shared__ float As[GBK][GBM + 4];
    __shared__ float Ws[GBK][GBN + 4];
    const int tid = threadIdx.x;
    const int row0 = blockIdx.y * GBM;
    const int col0 = blockIdx.x * GBN;
    const int m0 = (tid >> 4) * 8;      // 0..120
    const int n0 = (tid & 15) * 4;      // 0..60
    unsigned long long acc[8][2];
    #pragma unroll
    for (int i = 0; i < 8; i++) { acc[i][0] = 0ULL; acc[i][1] = 0ULL; }

    for (int k0 = 0; k0 < 512; k0 += GBK) {
        #pragma unroll
        for (int l = 0; l < 4; l++) {
            int t = tid + l * 256;
            int m = t & 127, kq = t >> 7;   // kq 0..7
            float4 v = *(const float4*)(A + (size_t)(row0 + m) * 512 + k0 + kq * 4);
            As[kq*4+0][m] = v.x; As[kq*4+1][m] = v.y;
            As[kq*4+2][m] = v.z; As[kq*4+3][m] = v.w;
        }
        #pragma unroll
        for (int l = 0; l < 2; l++) {
            int t = tid + l * 256;
            int n = t & 63, kq = t >> 6;    // kq 0..7
            float4 v = *(const float4*)(W + (size_t)(col0 + n) * 512 + k0 + kq * 4);
            Ws[kq*4+0][n] = v.x; Ws[kq*4+1][n] = v.y;
            Ws[kq*4+2][n] = v.z; Ws[kq*4+3][n] = v.w;
        }
        __syncthreads();
        #pragma unroll
        for (int k = 0; k < GBK; k++) {
            float4 a0 = *(const float4*)&As[k][m0];
            float4 a1 = *(const float4*)&As[k][m0 + 4];
            float4 wv = *(const float4*)&Ws[k][n0];
            unsigned long long w01, w23;
            PACK2(w01, wv.x, wv.y);
            PACK2(w23, wv.z, wv.w);
            float am[8] = {a0.x,a0.y,a0.z,a0.w,a1.x,a1.y,a1.z,a1.w};
            #pragma unroll
            for (int i = 0; i < 8; i++) {
                unsigned long long ai;
                BCAST2(ai, am[i]);
                FMA2(acc[i][0], ai, w01);
                FMA2(acc[i][1], ai, w23);
            }
        }
        __syncthreads();
    }
    float bv0 = 0.f, bv1 = 0.f, bv2 = 0.f, bv3 = 0.f;
    if (bias) {
        bv0 = bias[col0+n0]; bv1 = bias[col0+n0+1];
        bv2 = bias[col0+n0+2]; bv3 = bias[col0+n0+3];
    }
    #pragma unroll
    for (int i = 0; i < 8; i++) {
        float c0, c1, c2, c3;
        UNPK2(c0, c1, acc[i][0]);
        UNPK2(c2, c3, acc[i][1]);
        float4 o = {c0 + bv0, c1 + bv1, c2 + bv2, c3 + bv3};
        if (act == 1) {
            o.x = fminf(1.f, fmaxf(-1.f, o.x));
            o.y = fminf(1.f, fmaxf(-1.f, o.y));
            o.z = fminf(1.f, fmaxf(-1.f, o.z));
            o.w = fminf(1.f, fmaxf(-1.f, o.w));
        }
        *(float4*)(C + (size_t)(row0 + m0 + i) * N + col0 + n0) = o;
    }
}

// ======== GRU persistent recurrence (R9 sync structure, 1024 threads) =======
// grid=128 CTAs, 1024 thr (32 warps, 8/SMSP for latency hiding).
// CTA c owns h-columns [4c,4c+4) (12 gate cols).
// Warp w: lane=b, 16-k slice k0 = q*128 + (w&7)*16, q=((w>>3)+cta)&3.
// Slice spans 4 producer CTAs -> warp polls 4 per-CTA flags (lane&3).
// h read via ld.global.cg (coherent, MLP=16). Flags: single writer st.release.
#define SM_WP   0
#define SM_RED  32768
#define SM_BH   (32768 + 53248)
#define GRU_SMEM (32768 + 53248 + 64)

__global__ __launch_bounds__(1024)
void gru_kernel(const float* __restrict__ gi, const float* __restrict__ Whh,
                const float* __restrict__ bhh, float* __restrict__ st_out,
                int lay1) {
    extern __shared__ char sm[];
    float* wp  = (float*)(sm + SM_WP);    // [k][16] floats; cols c=0..11 (c=g*4+jl)
    float* red = (float*)(sm + SM_RED);   // [(w*32+b)*13 + c], 32 warps
    float* bh  = (float*)(sm + SM_BH);    // [12]
    const int tid = threadIdx.x;
    const int cta = blockIdx.x;

    unsigned* flg = lay1 ? g_flagB : g_flagA;
    // reset the OTHER layer's flag (only touched by the previous launch)
    if (tid == 0) (lay1 ? g_flagA : g_flagB)[cta * 32] = 0;

    // weights: wp[k*16 + c] = Whh[(g*512 + cta*4 + jl)*512 + k], c = g*4+jl
    for (int i = tid; i < 6144; i += 1024) {
        int c = i >> 9, k = i & 511;
        int g = c >> 2, jl = c & 3;
        wp[k * 16 + c] = Whh[(size_t)(g * 512 + cta * 4 + jl) * 512 + k];
    }
    if (tid < 12) bh[tid] = bhh[(tid >> 2) * 512 + cta * 4 + (tid & 3)];
    __syncthreads();

    const int lane = tid & 31, w = tid >> 5;
    const int q = ((w >> 3) + cta) & 3;          // chunk this warp consumes
    const int k0 = q * 128 + (w & 7) * 16;       // warp's 16-k slice
    const int pc0 = k0 >> 2;                     // first producer CTA of slice
    const unsigned* myflag = &flg[(pc0 + (lane & 3)) * 32];
    // gate-phase identity (tid < 128)
    const int bb = tid & 31, jl = (tid >> 5) & 3;
    const int jg = cta * 4 + jl;

    float giv0 = 0.f, giv1 = 0.f, giv2 = 0.f, ho = 0.f;
    if (tid < 128) {
        giv0 = __ldg(gi + (size_t)bb * G3 + jg);
        giv1 = __ldg(gi + (size_t)bb * G3 + 512 + jg);
        giv2 = __ldg(gi + (size_t)bb * G3 + 1024 + jg);
    }

    for (int s = 0; s < 128; s++) {
        if (s > 0) {
            // ---- warp-autonomous wait for THIS slice's 4 producers ----
            {
                unsigned tgt = (unsigned)s;
                while (!__all_sync(0xffffffffu, ld_acq(myflag) >= tgt)) { }
            }

            // ---- direct L2 read (cg): all 16 h loads in flight at once ----
            const float* hb = g_hT2 + ((s + 1) & 1) * (Hn * Bn) + (size_t)k0 * 32 + lane;
            float hr[16];
            #pragma unroll
            for (int i = 0; i < 16; i++) hr[i] = ldcg(hb + i * 32);

            unsigned long long acc[6];
            #pragma unroll
            for (int p = 0; p < 6; p++) acc[p] = 0ULL;
            #pragma unroll
            for (int i = 0; i < 16; i++) {
                unsigned long long h2;
                BCAST2(h2, hr[i]);
                const ulonglong2* wk = (const ulonglong2*)(wp + (k0 + i) * 16);
                ulonglong2 A = wk[0], Bv = wk[1], Cv = wk[2];
                FMA2(acc[0], h2, A.x);  FMA2(acc[1], h2, A.y);
                FMA2(acc[2], h2, Bv.x); FMA2(acc[3], h2, Bv.y);
                FMA2(acc[4], h2, Cv.x); FMA2(acc[5], h2, Cv.y);
            }
            float* rr = red + (w * 32 + lane) * 13;
            #pragma unroll
            for (int p = 0; p < 6; p++) {
                float x, y;
                UNPK2(x, y, acc[p]);
                rr[2 * p] = x; rr[2 * p + 1] = y;
            }
        }
        __syncthreads();

        // ---- gate math for the CTA's 4 columns ----
        float hn = 0.f;
        if (tid < 128) {
            float gh0 = 0.f, gh1 = 0.f, gh2 = 0.f;
            if (s > 0) {
                #pragma unroll
                for (int ww = 0; ww < 32; ww++) {
                    const float* rr = red + (ww * 32 + bb) * 13;
                    gh0 += rr[jl];
                    gh1 += rr[4 + jl];
                    gh2 += rr[8 + jl];
                }
            }
            float r = 1.f / (1.f + expf(-(giv0 + gh0 + bh[jl])));
            float z = 1.f / (1.f + expf(-(giv1 + gh1 + bh[4 + jl])));
            float nn = tanhf(giv2 + r * (gh2 + bh[8 + jl]));
            hn = (1.f - z) * nn + z * ho;
            ho = hn;
            g_hT2[(s & 1) * (Hn * Bn) + jg * 32 + bb] = hn;
        }
        __syncthreads();

        // ---- publish progress: ONE release store, no atomics ----
        if (tid == 0) st_rel(&flg[cta * 32], (unsigned)(s + 1));

        // ---- off-critical-path work: states write + next gi prefetch ----
        if (tid < 128) {
            size_t oidx = lay1 ? ((size_t)bb * 128 + s) * 512 + jg
                               : ((size_t)s * 32 + bb) * 512 + jg;
            st_out[oidx] = hn;
            if (s < 127) {
                size_t gib = ((size_t)(s + 1) * 32 + bb) * (size_t)G3;
                giv0 = __ldg(gi + gib + jg);
                giv1 = __ldg(gi + gib + 512 + jg);
                giv2 = __ldg(gi + gib + 1024 + jg);
            }
        }
    }
}

// ======== final: time-attention + linear + softmax ==========================
// states layout here: [b][s][h] (written directly by layer-1 GRU into d_out)
__global__ __launch_bounds__(256)
void final_kernel(const float* __restrict__ states, const float* __restrict__ attw,
                  const float* __restrict__ demoip, const float* __restrict__ linW,
                  const float* __restrict__ linb, float* __restrict__ out) {
    __shared__ float aw[512];
    __shared__ float lg[128];
    __shared__ float al[128];
    __shared__ float ctx[512];
    __shared__ float o10[10];
    const int tid = threadIdx.x, b = blockIdx.x;
    const int w = tid >> 5, lane = tid & 31;
    const float* stb = states + (size_t)b * 128 * 512;

    for (int h = tid; h < 512; h += 256) aw[h] = attw[h];
    __syncthreads();

    for (int s = w; s < 128; s += 8) {
        const float* row = stb + (size_t)s * 512;
        float acc = 0.f;
        for (int h = lane; h < 512; h += 32) acc += row[h] * aw[h];
        acc = wred(acc);
        if (lane == 0) lg[s] = acc;
    }
    __syncthreads();

    if (tid < 32) {
        float v[4]; float m = -1e30f;
        #pragma unroll
        for (int q = 0; q < 4; q++) { v[q] = lg[tid + q * 32]; m = fmaxf(m, v[q]); }
        #pragma unroll
        for (int o = 16; o; o >>= 1) m = fmaxf(m, __shfl_xor_sync(0xffffffffu, m, o));
        float ssum = 0.f;
        #pragma unroll
        for (int q = 0; q < 4; q++) { v[q] = expf(v[q] - m); ssum += v[q]; }
        ssum = wred(ssum);
        #pragma unroll
        for (int q = 0; q < 4; q++) {
            float a = v[q] / ssum;
            al[tid + q * 32] = a;
            out[OFF_AL + b * 128 + tid + q * 32] = a;
        }
    }
    __syncthreads();

    for (int h = tid; h < 512; h += 256) {
        float acc = 0.f;
        for (int s = 0; s < 128; s++) acc += al[s] * stb[(size_t)s * 512 + h];
        ctx[h] = acc;
        out[OFF_CTX + b * 512 + h] = acc;
    }
    __syncthreads();

    if (tid < 10) {
        float acc = linb[tid];
        const float* wrow = linW + tid * 515;
        for (int h = 0; h < 512; h++) acc += ctx[h] * wrow[h];
        for (int d = 0; d < 3; d++) acc += demoip[b * 3 + d] * wrow[512 + d];
        o10[tid] = acc;
    }
    __syncthreads();
    if (tid < 10) {
        float m = -1e30f;
        for (int o = 0; o < 10; o++) m = fmaxf(m, o10[o]);
        float e = expf(o10[tid] - m), ssum = 0.f;
        for (int o = 0; o < 10; o++) ssum += expf(o10[o] - m);
        out[OFF_OUT + b * 10 + tid] = e / ssum;
    }
}

// ======== launch ============================================================
extern "C" void kernel_launch(void* const* d_in, const int* in_sizes, int n_in,
                              void* d_out, int out_size) {
    // batch_size may or may not be materialized as input[2] (size-1 scalar).
    int sh = (in_sizes[2] == 1) ? 1 : 0;

    const float* inp   = (const float*)d_in[0];
    const float* demo  = (const float*)d_in[1];
    const float* convw = (const float*)d_in[2 + sh];
    // conv_b at [3+sh] cancels in the softmax; unused.
    const float* embW  = (const float*)d_in[4 + sh];
    const float* Wi0   = (const float*)d_in[5 + sh];
    const float* Wh0   = (const float*)d_in[6 + sh];
    const float* bi0   = (const float*)d_in[7 + sh];
    const float* bh0   = (const float*)d_in[8 + sh];
    const float* Wi1   = (const float*)d_in[9 + sh];
    const float* Wh1   = (const float*)d_in[10 + sh];
    const float* bi1   = (const float*)d_in[11 + sh];
    const float* bh1   = (const float*)d_in[12 + sh];
    const float* attw  = (const float*)d_in[13 + sh];
    const float* linW  = (const float*)d_in[14 + sh];
    const float* linb  = (const float*)d_in[15 + sh];
    float* out = (float*)d_out;

    cudaFuncSetAttribute(gru_kernel, cudaFuncAttributeMaxDynamicSharedMemorySize, GRU_SMEM);

    void *pc, *pe, *p0, *ps0, *p1;
    cudaGetSymbolAddress(&pc, g_conv);
    cudaGetSymbolAddress(&pe, g_emb);
    cudaGetSymbolAddress(&p0, g_gi0);
    cudaGetSymbolAddress(&ps0, g_st0);
    cudaGetSymbolAddress(&p1, g_gi1);

    conv_pool_kernel<<<Bn * Sn, 256>>>(inp, convw, (float*)pc);

    dim3 ge(In / GBN, (Sn * Bn) / GBM);   // (8, 32)
    dim3 gg(G3 / GBN, (Sn * Bn) / GBM);   // (24, 32)
    gemm_tn<<<ge, 256>>>((const float*)pc, embW, nullptr, (float*)pe, In, 1);
    gemm_tn<<<gg, 256>>>((const float*)pe, Wi0, bi0, (float*)p0, G3, 0);

    gru_kernel<<<128, 1024, GRU_SMEM>>>((const float*)p0, Wh0, bh0, (float*)ps0, 0);

    gemm_tn<<<gg, 256>>>((const float*)ps0, Wi1, bi1, (float*)p1, G3, 0);

    gru_kernel<<<128, 1024, GRU_SMEM>>>((const float*)p1, Wh1, bh1, out + OFF_ST, 1);

    final_kernel<<<Bn, 256>>>(out + OFF_ST, attw, demo, linW, linb, out);
}